// round 2
// baseline (speedup 1.0000x reference)
#include <cuda_runtime.h>
#include <cstdint>
#include <cstddef>

#define NN   2048
#define BB   32
#define COLS 8192   // B * F_IN * T = 32*16*16

// scratch: rhs[k][n][b*256 + f*16 + t]  (3*2048*8192 floats = 201 MB)
__device__ float g_rhs[50331648];

// ---------------------------------------------------------------------------
// helpers
// ---------------------------------------------------------------------------
__device__ __forceinline__ float to_tf32(float x) {
    uint32_t u;
    asm("cvt.rna.tf32.f32 %0, %1;" : "=r"(u) : "f"(x));
    return __uint_as_float(u);
}

__device__ __forceinline__ float4 tf4(float4 v) {
    return make_float4(to_tf32(v.x), to_tf32(v.y), to_tf32(v.z), to_tf32(v.w));
}

__device__ __forceinline__ void mma4(float (&d)[4], const float (&a)[4], const float (&b)[2]) {
    const uint32_t* A = reinterpret_cast<const uint32_t*>(a);
    const uint32_t* B = reinterpret_cast<const uint32_t*>(b);
    asm volatile(
        "mma.sync.aligned.m16n8k8.row.col.f32.tf32.tf32.f32 "
        "{%0,%1,%2,%3},{%4,%5,%6,%7},{%8,%9},{%0,%1,%2,%3};\n"
        : "+f"(d[0]), "+f"(d[1]), "+f"(d[2]), "+f"(d[3])
        : "r"(A[0]), "r"(A[1]), "r"(A[2]), "r"(A[3]), "r"(B[0]), "r"(B[1]));
}

// ---------------------------------------------------------------------------
// Kernel 1: rhs[k][n][col] = sum_m cheb[k][m][n] * x[b][m][f][t],  col=(b,f,t)
// Tile: BM=128 (n), BN=128 (col), BK=16 (m). 256 threads, 8 warps (2x4),
// warp tile 64x32 via tf32 mma.m16n8k8. Double-buffered smem.
// ---------------------------------------------------------------------------
__global__ __launch_bounds__(256) void gemm_k(const float* __restrict__ cheb,
                                              const float* __restrict__ xg) {
    __shared__ float As[2][16][132];   // [buf][m][n]  (A^T tile = cheb tile as-is)
    __shared__ float Bs[2][16][132];   // [buf][m][col]

    const int k    = blockIdx.z;
    const int n0   = blockIdx.y * 128;
    const int col0 = blockIdx.x * 128;
    const int b    = col0 >> 8;        // 256 cols per batch element
    const int coff = col0 & 255;       // 0 or 128

    const int tid  = threadIdx.x;
    const int lane = tid & 31;
    const int warp = tid >> 5;
    const int wm   = (warp & 1) * 64;
    const int wn   = (warp >> 1) * 32;
    const int gid  = lane >> 2;        // groupID
    const int tig  = lane & 3;         // threadID_in_group
    const int n4   = tid & 31;         // float4 column for staging
    const int mr   = tid >> 5;         // staging row 0..7 (and +8)

    const float* Ag = cheb + (size_t)k * NN * NN + (size_t)mr * NN + n0 + n4 * 4;
    const float* Bg = xg + ((size_t)b * NN + mr) * 256 + coff + n4 * 4;

    float acc[4][4][4];
#pragma unroll
    for (int i = 0; i < 4; i++)
#pragma unroll
        for (int j = 0; j < 4; j++)
#pragma unroll
            for (int q = 0; q < 4; q++) acc[i][j][q] = 0.f;

    float4 pa0, pa1, pb0, pb1;
    // prefetch tile 0
    pa0 = *(const float4*)(Ag);
    pa1 = *(const float4*)(Ag + (size_t)8 * NN);
    pb0 = *(const float4*)(Bg);
    pb1 = *(const float4*)(Bg + 8 * 256);

    // stage tile 0 (rounded to tf32)
    *(float4*)&As[0][mr][n4 * 4]     = tf4(pa0);
    *(float4*)&As[0][mr + 8][n4 * 4] = tf4(pa1);
    *(float4*)&Bs[0][mr][n4 * 4]     = tf4(pb0);
    *(float4*)&Bs[0][mr + 8][n4 * 4] = tf4(pb1);
    __syncthreads();

    const int NIT = NN / 16;   // 128
    for (int it = 0; it < NIT; ++it) {
        const int buf = it & 1;
        if (it + 1 < NIT) {
            const size_t moff = (size_t)(it + 1) * 16;
            pa0 = *(const float4*)(Ag + moff * NN);
            pa1 = *(const float4*)(Ag + (moff + 8) * NN);
            pb0 = *(const float4*)(Bg + moff * 256);
            pb1 = *(const float4*)(Bg + (moff + 8) * 256);
        }
#pragma unroll
        for (int kk = 0; kk < 2; ++kk) {
            const int c0 = kk * 8 + tig;
            const int c1 = c0 + 4;
            float a[4][4];
            float bf[4][2];
#pragma unroll
            for (int fm = 0; fm < 4; ++fm) {
                const int r0 = wm + fm * 16 + gid;
                a[fm][0] = As[buf][c0][r0];
                a[fm][1] = As[buf][c0][r0 + 8];
                a[fm][2] = As[buf][c1][r0];
                a[fm][3] = As[buf][c1][r0 + 8];
            }
#pragma unroll
            for (int fn = 0; fn < 4; ++fn) {
                const int cc = wn + fn * 8 + gid;
                bf[fn][0] = Bs[buf][c0][cc];
                bf[fn][1] = Bs[buf][c1][cc];
            }
#pragma unroll
            for (int fm = 0; fm < 4; ++fm)
#pragma unroll
                for (int fn = 0; fn < 4; ++fn) mma4(acc[fm][fn], a[fm], bf[fn]);
        }
        if (it + 1 < NIT) {
            const int nb = buf ^ 1;
            *(float4*)&As[nb][mr][n4 * 4]     = tf4(pa0);
            *(float4*)&As[nb][mr + 8][n4 * 4] = tf4(pa1);
            *(float4*)&Bs[nb][mr][n4 * 4]     = tf4(pb0);
            *(float4*)&Bs[nb][mr + 8][n4 * 4] = tf4(pb1);
            __syncthreads();
        }
    }

    float* Cg = g_rhs + (size_t)k * NN * COLS;
#pragma unroll
    for (int fm = 0; fm < 4; ++fm) {
        const int r = n0 + wm + fm * 16 + gid;
#pragma unroll
        for (int fn = 0; fn < 4; ++fn) {
            const int cc = col0 + wn + fn * 8 + tig * 2;
            *(float2*)(Cg + (size_t)r * COLS + cc)       = make_float2(acc[fm][fn][0], acc[fm][fn][1]);
            *(float2*)(Cg + (size_t)(r + 8) * COLS + cc) = make_float2(acc[fm][fn][2], acc[fm][fn][3]);
        }
    }
}

// ---------------------------------------------------------------------------
// Kernel 2: fused Theta-contraction + ReLU + time conv(1x3,pad1) + residual
//           1x1 conv + ReLU + LayerNorm(C) + output transpose.
// Block: 256 threads = 64 c-lanes x 4 n-lanes; 16 n per block (4 passes).
// ---------------------------------------------------------------------------
__global__ __launch_bounds__(256) void epi_k(const float* __restrict__ xg,
                                             const float* __restrict__ Theta,
                                             const float* __restrict__ tw,
                                             const float* __restrict__ tb,
                                             const float* __restrict__ rsw,
                                             const float* __restrict__ rsb,
                                             const float* __restrict__ lg,
                                             const float* __restrict__ lb,
                                             float* __restrict__ out) {
    __shared__ float Th[3072];        // Theta [k*16+f][o], o contiguous (12 KB)
    __shared__ float U[4096];         // union: R[4][768] + X[4][256]  /  H[4][16][64]
    __shared__ float S[4][64][20];    // spatial[nl][ci][t], row stride 20 (20 KB)

    const int tid   = threadIdx.x;
    const int c     = tid & 63;
    const int nl    = tid >> 6;
    const int b     = blockIdx.x >> 7;          // 128 blocks per batch element
    const int nbase = (blockIdx.x & 127) * 16;
    const int lane  = tid & 31;

#pragma unroll
    for (int j = 0; j < 12; j++) Th[tid + j * 256] = Theta[tid + j * 256];

    float rw[16];
#pragma unroll
    for (int f = 0; f < 16; f++) rw[f] = rsw[c * 16 + f];
    const float bias0 = tb[c] + rsb[c];

    const float g1 = lg[lane], g2 = lg[lane + 32];
    const float be1 = lb[lane], be2 = lb[lane + 32];

    for (int p = 0; p < 4; ++p) {
        // ---- cooperative load: rhs chunks (768 floats per n) and x (256 per n)
#pragma unroll
        for (int j = 0; j < 3; j++) {
            const int idx = tid + j * 256;        // float4 index 0..767
            const int nll = idx / 192;
            const int li  = idx % 192;
            const int kk  = li >> 6;
            const int r4  = li & 63;
            const int nn  = nbase + p * 4 + nll;
            const float4 v = *(const float4*)(g_rhs + ((size_t)kk * NN + nn) * COLS +
                                              (size_t)b * 256 + r4 * 4);
            *(float4*)(U + idx * 4) = v;
        }
        {
            const int nll = tid >> 6, r4 = tid & 63;
            const int nn  = nbase + p * 4 + nll;
            const float4 v = *(const float4*)(xg + ((size_t)b * NN + nn) * 256 + r4 * 4);
            *(float4*)(U + 3072 + tid * 4) = v;
        }
        __syncthreads();

        // ---- spatial[o=c][t] = relu( sum_kf Theta[kf][c] * R[kf][t] )
        float s[16];
#pragma unroll
        for (int t = 0; t < 16; t++) s[t] = 0.f;
        const float* Rr = U + nl * 768;
#pragma unroll 6
        for (int kf = 0; kf < 48; ++kf) {
            const float w  = Th[kf * 64 + c];
            const float4 q0 = *(const float4*)(Rr + kf * 16);
            const float4 q1 = *(const float4*)(Rr + kf * 16 + 4);
            const float4 q2 = *(const float4*)(Rr + kf * 16 + 8);
            const float4 q3 = *(const float4*)(Rr + kf * 16 + 12);
            s[0] += w * q0.x;  s[1] += w * q0.y;  s[2]  += w * q0.z;  s[3]  += w * q0.w;
            s[4] += w * q1.x;  s[5] += w * q1.y;  s[6]  += w * q1.z;  s[7]  += w * q1.w;
            s[8] += w * q2.x;  s[9] += w * q2.y;  s[10] += w * q2.z;  s[11] += w * q2.w;
            s[12] += w * q3.x; s[13] += w * q3.y; s[14] += w * q3.z;  s[15] += w * q3.w;
        }
#pragma unroll
        for (int q = 0; q < 4; q++) {
            *(float4*)(&S[nl][c][q * 4]) =
                make_float4(fmaxf(s[q * 4], 0.f), fmaxf(s[q * 4 + 1], 0.f),
                            fmaxf(s[q * 4 + 2], 0.f), fmaxf(s[q * 4 + 3], 0.f));
        }
        __syncthreads();

        // ---- h[t] = (time_b+res_b) + residual 1x1 + time conv (1x3, pad 1)
        float h[16];
#pragma unroll
        for (int t = 0; t < 16; t++) h[t] = bias0;

        const float* Xr = U + 3072 + nl * 256;
#pragma unroll
        for (int f = 0; f < 16; f++) {
            const float w  = rw[f];
            const float4 q0 = *(const float4*)(Xr + f * 16);
            const float4 q1 = *(const float4*)(Xr + f * 16 + 4);
            const float4 q2 = *(const float4*)(Xr + f * 16 + 8);
            const float4 q3 = *(const float4*)(Xr + f * 16 + 12);
            h[0] += w * q0.x;  h[1] += w * q0.y;  h[2]  += w * q0.z;  h[3]  += w * q0.w;
            h[4] += w * q1.x;  h[5] += w * q1.y;  h[6]  += w * q1.z;  h[7]  += w * q1.w;
            h[8] += w * q2.x;  h[9] += w * q2.y;  h[10] += w * q2.z;  h[11] += w * q2.w;
            h[12] += w * q3.x; h[13] += w * q3.y; h[14] += w * q3.z;  h[15] += w * q3.w;
        }

#pragma unroll 2
        for (int ci = 0; ci < 64; ++ci) {
            const float* wp = tw + (c * 64 + ci) * 3;
            const float w0 = __ldg(wp), w1 = __ldg(wp + 1), w2 = __ldg(wp + 2);
            const float* Sr = &S[nl][ci][0];
            const float4 a0 = *(const float4*)(Sr);
            const float4 a1 = *(const float4*)(Sr + 4);
            const float4 a2 = *(const float4*)(Sr + 8);
            const float4 a3 = *(const float4*)(Sr + 12);
            const float sv[16] = {a0.x, a0.y, a0.z, a0.w, a1.x, a1.y, a1.z, a1.w,
                                  a2.x, a2.y, a2.z, a2.w, a3.x, a3.y, a3.z, a3.w};
#pragma unroll
            for (int t = 0; t < 16; t++) {
                float a = w1 * sv[t];
                if (t > 0)  a += w0 * sv[t - 1];
                if (t < 15) a += w2 * sv[t + 1];
                h[t] += a;
            }
        }
        __syncthreads();   // everyone done reading U (X) and S

        // ---- stage h = relu(.) into H[nl][t][c] (aliases R/X region)
#pragma unroll
        for (int t = 0; t < 16; t++) U[nl * 1024 + t * 64 + c] = fmaxf(h[t], 0.f);
        __syncthreads();

        // ---- LayerNorm over c (64) per (nl, t); 8 warps x 8 columns
#pragma unroll
        for (int i = 0; i < 8; i++) {
            const int q   = (tid >> 5) * 8 + i;
            const int qnl = q >> 4, qt = q & 15;
            const float v1 = U[qnl * 1024 + qt * 64 + lane];
            const float v2 = U[qnl * 1024 + qt * 64 + lane + 32];
            float sm = v1 + v2, sq = v1 * v1 + v2 * v2;
#pragma unroll
            for (int o = 16; o > 0; o >>= 1) {
                sm += __shfl_xor_sync(0xffffffffu, sm, o);
                sq += __shfl_xor_sync(0xffffffffu, sq, o);
            }
            const float mu  = sm * 0.015625f;
            const float var = sq * 0.015625f - mu * mu;
            const float rs  = rsqrtf(var + 1e-5f);
            const int nn = nbase + p * 4 + qnl;
            float* ob = out + (((size_t)b * NN + nn) * 64) * 16 + qt;
            ob[(size_t)lane * 16]        = (v1 - mu) * rs * g1 + be1;
            ob[(size_t)(lane + 32) * 16] = (v2 - mu) * rs * g2 + be2;
        }
        __syncthreads();   // before next pass overwrites U
    }
}

// ---------------------------------------------------------------------------
extern "C" void kernel_launch(void* const* d_in, const int* in_sizes, int n_in,
                              void* d_out, int out_size) {
    const float* x      = (const float*)d_in[0];
    const float* cheb   = (const float*)d_in[1];
    const float* Theta  = (const float*)d_in[2];
    const float* time_w = (const float*)d_in[3];
    const float* time_b = (const float*)d_in[4];
    const float* res_w  = (const float*)d_in[5];
    const float* res_b  = (const float*)d_in[6];
    const float* ln_g   = (const float*)d_in[7];
    const float* ln_b   = (const float*)d_in[8];
    float* out = (float*)d_out;

    dim3 g1(COLS / 128, NN / 128, 3);   // 64 x 16 x 3
    gemm_k<<<g1, 256>>>(cheb, x);
    epi_k<<<4096, 256>>>(x, Theta, time_w, time_b, res_w, res_b, ln_g, ln_b, out);
}

// round 3
// speedup vs baseline: 1.0268x; 1.0268x over previous
#include <cuda_runtime.h>
#include <cstdint>
#include <cstddef>

#define NN   2048
#define BB   32
#define COLS 8192   // B * F_IN * T = 32*16*16

// scratch: rhs[k][n][b*256 + f*16 + t]  (3*2048*8192 floats = 201 MB)
__device__ float g_rhs[50331648];

// ---------------------------------------------------------------------------
// helpers
// ---------------------------------------------------------------------------
__device__ __forceinline__ float to_tf32(float x) {
    uint32_t u;
    asm("cvt.rna.tf32.f32 %0, %1;" : "=r"(u) : "f"(x));
    return __uint_as_float(u);
}

__device__ __forceinline__ float4 tf4(float4 v) {
    return make_float4(to_tf32(v.x), to_tf32(v.y), to_tf32(v.z), to_tf32(v.w));
}

__device__ __forceinline__ void mma4(float (&d)[4], const float (&a)[4], const float (&b)[2]) {
    const uint32_t* A = reinterpret_cast<const uint32_t*>(a);
    const uint32_t* B = reinterpret_cast<const uint32_t*>(b);
    asm volatile(
        "mma.sync.aligned.m16n8k8.row.col.f32.tf32.tf32.f32 "
        "{%0,%1,%2,%3},{%4,%5,%6,%7},{%8,%9},{%0,%1,%2,%3};\n"
        : "+f"(d[0]), "+f"(d[1]), "+f"(d[2]), "+f"(d[3])
        : "r"(A[0]), "r"(A[1]), "r"(A[2]), "r"(A[3]), "r"(B[0]), "r"(B[1]));
}

// ---------------------------------------------------------------------------
// Kernel 1: rhs[k][n][col] = sum_m cheb[k][m][n] * x[b][m][f][t],  col=(b,f,t)
// Tile: BM=128 (n), BN=128 (col), BK=16 (m). 256 threads, 8 warps (2x4),
// warp tile 64x32 via tf32 mma.m16n8k8. Double-buffered smem.
// ---------------------------------------------------------------------------
__global__ __launch_bounds__(256) void gemm_k(const float* __restrict__ cheb,
                                              const float* __restrict__ xg) {
    __shared__ float As[2][16][132];   // [buf][m][n]  (A^T tile = cheb tile as-is)
    __shared__ float Bs[2][16][132];   // [buf][m][col]

    const int k    = blockIdx.z;
    const int n0   = blockIdx.y * 128;
    const int col0 = blockIdx.x * 128;
    const int b    = col0 >> 8;        // 256 cols per batch element
    const int coff = col0 & 255;       // 0 or 128

    const int tid  = threadIdx.x;
    const int lane = tid & 31;
    const int warp = tid >> 5;
    const int wm   = (warp & 1) * 64;
    const int wn   = (warp >> 1) * 32;
    const int gid  = lane >> 2;        // groupID
    const int tig  = lane & 3;         // threadID_in_group
    const int n4   = tid & 31;         // float4 column for staging
    const int mr   = tid >> 5;         // staging row 0..7 (and +8)

    const float* Ag = cheb + (size_t)k * NN * NN + (size_t)mr * NN + n0 + n4 * 4;
    const float* Bg = xg + ((size_t)b * NN + mr) * 256 + coff + n4 * 4;

    float acc[4][4][4];
#pragma unroll
    for (int i = 0; i < 4; i++)
#pragma unroll
        for (int j = 0; j < 4; j++)
#pragma unroll
            for (int q = 0; q < 4; q++) acc[i][j][q] = 0.f;

    float4 pa0, pa1, pb0, pb1;
    // prefetch tile 0
    pa0 = *(const float4*)(Ag);
    pa1 = *(const float4*)(Ag + (size_t)8 * NN);
    pb0 = *(const float4*)(Bg);
    pb1 = *(const float4*)(Bg + 8 * 256);

    // stage tile 0 (rounded to tf32)
    *(float4*)&As[0][mr][n4 * 4]     = tf4(pa0);
    *(float4*)&As[0][mr + 8][n4 * 4] = tf4(pa1);
    *(float4*)&Bs[0][mr][n4 * 4]     = tf4(pb0);
    *(float4*)&Bs[0][mr + 8][n4 * 4] = tf4(pb1);
    __syncthreads();

    const int NIT = NN / 16;   // 128
    for (int it = 0; it < NIT; ++it) {
        const int buf = it & 1;
        if (it + 1 < NIT) {
            const size_t moff = (size_t)(it + 1) * 16;
            pa0 = *(const float4*)(Ag + moff * NN);
            pa1 = *(const float4*)(Ag + (moff + 8) * NN);
            pb0 = *(const float4*)(Bg + moff * 256);
            pb1 = *(const float4*)(Bg + (moff + 8) * 256);
        }
#pragma unroll
        for (int kk = 0; kk < 2; ++kk) {
            const int c0 = kk * 8 + tig;
            const int c1 = c0 + 4;
            float a[4][4];
            float bf[4][2];
#pragma unroll
            for (int fm = 0; fm < 4; ++fm) {
                const int r0 = wm + fm * 16 + gid;
                a[fm][0] = As[buf][c0][r0];
                a[fm][1] = As[buf][c0][r0 + 8];
                a[fm][2] = As[buf][c1][r0];
                a[fm][3] = As[buf][c1][r0 + 8];
            }
#pragma unroll
            for (int fn = 0; fn < 4; ++fn) {
                const int cc = wn + fn * 8 + gid;
                bf[fn][0] = Bs[buf][c0][cc];
                bf[fn][1] = Bs[buf][c1][cc];
            }
#pragma unroll
            for (int fm = 0; fm < 4; ++fm)
#pragma unroll
                for (int fn = 0; fn < 4; ++fn) mma4(acc[fm][fn], a[fm], bf[fn]);
        }
        if (it + 1 < NIT) {
            const int nb = buf ^ 1;
            *(float4*)&As[nb][mr][n4 * 4]     = tf4(pa0);
            *(float4*)&As[nb][mr + 8][n4 * 4] = tf4(pa1);
            *(float4*)&Bs[nb][mr][n4 * 4]     = tf4(pb0);
            *(float4*)&Bs[nb][mr + 8][n4 * 4] = tf4(pb1);
            __syncthreads();
        }
    }

    float* Cg = g_rhs + (size_t)k * NN * COLS;
#pragma unroll
    for (int fm = 0; fm < 4; ++fm) {
        const int r = n0 + wm + fm * 16 + gid;
#pragma unroll
        for (int fn = 0; fn < 4; ++fn) {
            const int cc = col0 + wn + fn * 8 + tig * 2;
            *(float2*)(Cg + (size_t)r * COLS + cc)       = make_float2(acc[fm][fn][0], acc[fm][fn][1]);
            *(float2*)(Cg + (size_t)(r + 8) * COLS + cc) = make_float2(acc[fm][fn][2], acc[fm][fn][3]);
        }
    }
}

// ---------------------------------------------------------------------------
// Kernel 2: fused Theta-contraction + ReLU + time conv(1x3,pad1) + residual
//           1x1 conv + ReLU + LayerNorm(C) + output transpose.
// Block: 256 threads = 64 c-lanes x 4 n-lanes; 16 n per block (4 passes).
// R2: batched conv weight prefetch (MLP 24), coalesced output via smem stage.
// ---------------------------------------------------------------------------
__global__ __launch_bounds__(256) void epi_k(const float* __restrict__ xg,
                                             const float* __restrict__ Theta,
                                             const float* __restrict__ tw,
                                             const float* __restrict__ tb,
                                             const float* __restrict__ rsw,
                                             const float* __restrict__ rsb,
                                             const float* __restrict__ lg,
                                             const float* __restrict__ lb,
                                             float* __restrict__ out) {
    __shared__ float Th[3072];        // Theta [k*16+f][o], o contiguous (12 KB)
    __shared__ float U[4096];         // union: R[4][768] + X[4][256]  /  H[4][16][64]
    __shared__ float S[4][64][20];    // spatial[nl][ci][t] (20 KB); aliased as LN stage

    float* Sln = &S[0][0][0];         // LN stage: [qnl][c*17 + t], 4*1088 floats

    const int tid   = threadIdx.x;
    const int c     = tid & 63;
    const int nl    = tid >> 6;
    const int b     = blockIdx.x >> 7;          // 128 blocks per batch element
    const int nbase = (blockIdx.x & 127) * 16;
    const int lane  = tid & 31;

#pragma unroll
    for (int j = 0; j < 12; j++) Th[tid + j * 256] = Theta[tid + j * 256];

    float rw[16];
#pragma unroll
    for (int f = 0; f < 16; f++) rw[f] = rsw[c * 16 + f];
    const float bias0 = tb[c] + rsb[c];

    const float g1 = lg[lane], g2 = lg[lane + 32];
    const float be1 = lb[lane], be2 = lb[lane + 32];

    for (int p = 0; p < 4; ++p) {
        // ---- cooperative load: rhs chunks (768 floats per n) and x (256 per n)
#pragma unroll
        for (int j = 0; j < 3; j++) {
            const int idx = tid + j * 256;        // float4 index 0..767
            const int nll = idx / 192;
            const int li  = idx % 192;
            const int kk  = li >> 6;
            const int r4  = li & 63;
            const int nn  = nbase + p * 4 + nll;
            const float4 v = *(const float4*)(g_rhs + ((size_t)kk * NN + nn) * COLS +
                                              (size_t)b * 256 + r4 * 4);
            *(float4*)(U + idx * 4) = v;
        }
        {
            const int nll = tid >> 6, r4 = tid & 63;
            const int nn  = nbase + p * 4 + nll;
            const float4 v = *(const float4*)(xg + ((size_t)b * NN + nn) * 256 + r4 * 4);
            *(float4*)(U + 3072 + tid * 4) = v;
        }
        __syncthreads();

        // ---- spatial[o=c][t] = relu( sum_kf Theta[kf][c] * R[kf][t] )
        float s[16];
#pragma unroll
        for (int t = 0; t < 16; t++) s[t] = 0.f;
        const float* Rr = U + nl * 768;
#pragma unroll 8
        for (int kf = 0; kf < 48; ++kf) {
            const float w  = Th[kf * 64 + c];
            const float4 q0 = *(const float4*)(Rr + kf * 16);
            const float4 q1 = *(const float4*)(Rr + kf * 16 + 4);
            const float4 q2 = *(const float4*)(Rr + kf * 16 + 8);
            const float4 q3 = *(const float4*)(Rr + kf * 16 + 12);
            s[0] += w * q0.x;  s[1] += w * q0.y;  s[2]  += w * q0.z;  s[3]  += w * q0.w;
            s[4] += w * q1.x;  s[5] += w * q1.y;  s[6]  += w * q1.z;  s[7]  += w * q1.w;
            s[8] += w * q2.x;  s[9] += w * q2.y;  s[10] += w * q2.z;  s[11] += w * q2.w;
            s[12] += w * q3.x; s[13] += w * q3.y; s[14] += w * q3.z;  s[15] += w * q3.w;
        }
#pragma unroll
        for (int q = 0; q < 4; q++) {
            *(float4*)(&S[nl][c][q * 4]) =
                make_float4(fmaxf(s[q * 4], 0.f), fmaxf(s[q * 4 + 1], 0.f),
                            fmaxf(s[q * 4 + 2], 0.f), fmaxf(s[q * 4 + 3], 0.f));
        }
        __syncthreads();

        // ---- h[t] = (time_b+res_b) + residual 1x1 + time conv (1x3, pad 1)
        float h[16];
#pragma unroll
        for (int t = 0; t < 16; t++) h[t] = bias0;

        const float* Xr = U + 3072 + nl * 256;
#pragma unroll
        for (int f = 0; f < 16; f++) {
            const float w  = rw[f];
            const float4 q0 = *(const float4*)(Xr + f * 16);
            const float4 q1 = *(const float4*)(Xr + f * 16 + 4);
            const float4 q2 = *(const float4*)(Xr + f * 16 + 8);
            const float4 q3 = *(const float4*)(Xr + f * 16 + 12);
            h[0] += w * q0.x;  h[1] += w * q0.y;  h[2]  += w * q0.z;  h[3]  += w * q0.w;
            h[4] += w * q1.x;  h[5] += w * q1.y;  h[6]  += w * q1.z;  h[7]  += w * q1.w;
            h[8] += w * q2.x;  h[9] += w * q2.y;  h[10] += w * q2.z;  h[11] += w * q2.w;
            h[12] += w * q3.x; h[13] += w * q3.y; h[14] += w * q3.z;  h[15] += w * q3.w;
        }

        // time conv: process ci in chunks of 8, batch the 24 weight loads first
        // (L1-resident 48 KB tensor, MLP=24 hides the latency).
#pragma unroll
        for (int cb = 0; cb < 64; cb += 8) {
            float wr[24];
#pragma unroll
            for (int j = 0; j < 8; j++) {
                const float* wp = tw + (c * 64 + cb + j) * 3;
                wr[j * 3 + 0] = __ldg(wp);
                wr[j * 3 + 1] = __ldg(wp + 1);
                wr[j * 3 + 2] = __ldg(wp + 2);
            }
#pragma unroll
            for (int j = 0; j < 8; j++) {
                const float w0 = wr[j * 3], w1 = wr[j * 3 + 1], w2 = wr[j * 3 + 2];
                const float* Sr = &S[nl][cb + j][0];
                const float4 a0 = *(const float4*)(Sr);
                const float4 a1 = *(const float4*)(Sr + 4);
                const float4 a2 = *(const float4*)(Sr + 8);
                const float4 a3 = *(const float4*)(Sr + 12);
                const float sv[16] = {a0.x, a0.y, a0.z, a0.w, a1.x, a1.y, a1.z, a1.w,
                                      a2.x, a2.y, a2.z, a2.w, a3.x, a3.y, a3.z, a3.w};
#pragma unroll
                for (int t = 0; t < 16; t++) {
                    float a = w1 * sv[t];
                    if (t > 0)  a += w0 * sv[t - 1];
                    if (t < 15) a += w2 * sv[t + 1];
                    h[t] += a;
                }
            }
        }
        __syncthreads();   // everyone done reading U (X) and S

        // ---- stage h = relu(.) into H[nl][t][c] (aliases R/X region)
#pragma unroll
        for (int t = 0; t < 16; t++) U[nl * 1024 + t * 64 + c] = fmaxf(h[t], 0.f);
        __syncthreads();

        // ---- LayerNorm over c (64) per (nl, t); write normalized to Sln stage
#pragma unroll
        for (int i = 0; i < 8; i++) {
            const int q   = (tid >> 5) * 8 + i;
            const int qnl = q >> 4, qt = q & 15;
            const float v1 = U[qnl * 1024 + qt * 64 + lane];
            const float v2 = U[qnl * 1024 + qt * 64 + lane + 32];
            float sm = v1 + v2, sq = v1 * v1 + v2 * v2;
#pragma unroll
            for (int o = 16; o > 0; o >>= 1) {
                sm += __shfl_xor_sync(0xffffffffu, sm, o);
                sq += __shfl_xor_sync(0xffffffffu, sq, o);
            }
            const float mu  = sm * 0.015625f;
            const float var = sq * 0.015625f - mu * mu;
            const float rs  = rsqrtf(var + 1e-5f);
            // Sln layout: [qnl][c*17 + t] (pad 17 -> conflict-free)
            Sln[qnl * 1088 + lane * 17 + qt]        = (v1 - mu) * rs * g1 + be1;
            Sln[qnl * 1088 + (lane + 32) * 17 + qt] = (v2 - mu) * rs * g2 + be2;
        }
        __syncthreads();

        // ---- coalesced copy-out: 4096 contiguous floats (out[b][nn][c][t])
        {
            float* ob = out + (((size_t)b * NN + nbase + p * 4) << 10);
#pragma unroll
            for (int j = 0; j < 16; j++) {
                const int idx = tid + j * 256;      // 0..4095
                const int qnl = idx >> 10;
                const int rem = idx & 1023;         // c*16 + t
                const int cc  = rem >> 4;
                const int tt  = rem & 15;
                ob[idx] = Sln[qnl * 1088 + cc * 17 + tt];
            }
        }
        __syncthreads();   // before next pass overwrites U / S
    }
}

// ---------------------------------------------------------------------------
extern "C" void kernel_launch(void* const* d_in, const int* in_sizes, int n_in,
                              void* d_out, int out_size) {
    const float* x      = (const float*)d_in[0];
    const float* cheb   = (const float*)d_in[1];
    const float* Theta  = (const float*)d_in[2];
    const float* time_w = (const float*)d_in[3];
    const float* time_b = (const float*)d_in[4];
    const float* res_w  = (const float*)d_in[5];
    const float* res_b  = (const float*)d_in[6];
    const float* ln_g   = (const float*)d_in[7];
    const float* ln_b   = (const float*)d_in[8];
    float* out = (float*)d_out;

    dim3 g1(COLS / 128, NN / 128, 3);   // 64 x 16 x 3
    gemm_k<<<g1, 256>>>(cheb, x);
    epi_k<<<4096, 256>>>(x, Theta, time_w, time_b, res_w, res_b, ln_g, ln_b, out);
}

// round 5
// speedup vs baseline: 1.9327x; 1.8823x over previous
#include <cuda_runtime.h>
#include <cstdint>
#include <cstddef>

#define NN   2048
#define BB   32
#define COLS 8192   // B * F_IN * T = 32*16*16

// scratch: rhs[k][n][b*256 + f*16 + t]  (3*2048*8192 floats = 201 MB)
__device__ float g_rhs[50331648];
// transposed time-conv weights: g_twT[(ci*3+dt)*64 + c]  (48 KB, L1-resident)
__device__ float g_twT[12288];

// ---------------------------------------------------------------------------
// helpers
// ---------------------------------------------------------------------------
__device__ __forceinline__ float to_tf32(float x) {
    uint32_t u;
    asm("cvt.rna.tf32.f32 %0, %1;" : "=r"(u) : "f"(x));
    return __uint_as_float(u);
}

__device__ __forceinline__ float4 tf4(float4 v) {
    return make_float4(to_tf32(v.x), to_tf32(v.y), to_tf32(v.z), to_tf32(v.w));
}

__device__ __forceinline__ void mma4(float (&d)[4], const float (&a)[4], const float (&b)[2]) {
    const uint32_t* A = reinterpret_cast<const uint32_t*>(a);
    const uint32_t* B = reinterpret_cast<const uint32_t*>(b);
    asm volatile(
        "mma.sync.aligned.m16n8k8.row.col.f32.tf32.tf32.f32 "
        "{%0,%1,%2,%3},{%4,%5,%6,%7},{%8,%9},{%0,%1,%2,%3};\n"
        : "+f"(d[0]), "+f"(d[1]), "+f"(d[2]), "+f"(d[3])
        : "r"(A[0]), "r"(A[1]), "r"(A[2]), "r"(A[3]), "r"(B[0]), "r"(B[1]));
}

// ---------------------------------------------------------------------------
// Kernel 0: transpose time_w (c-major -> c-minor) so epi_k weight loads are
// lane-coalesced (1 L1 wavefront instead of 32).
// ---------------------------------------------------------------------------
__global__ __launch_bounds__(256) void tr_k(const float* __restrict__ tw) {
    const int i = blockIdx.x * 256 + threadIdx.x;   // i = c*192 + (ci*3+dt)
    const int c = i / 192;
    const int r = i % 192;
    g_twT[r * 64 + c] = tw[i];
}

// ---------------------------------------------------------------------------
// Kernel 1: rhs[k][n][col] = sum_m cheb[k][m][n] * x[b][m][f][t],  col=(b,f,t)
// Tile: BM=128 (n), BN=128 (col), BK=16 (m). 256 threads, 8 warps (2x4),
// warp tile 64x32 via tf32 mma.m16n8k8. Double-buffered smem.
// ---------------------------------------------------------------------------
__global__ __launch_bounds__(256) void gemm_k(const float* __restrict__ cheb,
                                              const float* __restrict__ xg) {
    __shared__ float As[2][16][132];   // [buf][m][n]  (A^T tile = cheb tile as-is)
    __shared__ float Bs[2][16][132];   // [buf][m][col]

    const int k    = blockIdx.z;
    const int n0   = blockIdx.y * 128;
    const int col0 = blockIdx.x * 128;
    const int b    = col0 >> 8;        // 256 cols per batch element
    const int coff = col0 & 255;       // 0 or 128

    const int tid  = threadIdx.x;
    const int lane = tid & 31;
    const int warp = tid >> 5;
    const int wm   = (warp & 1) * 64;
    const int wn   = (warp >> 1) * 32;
    const int gid  = lane >> 2;        // groupID
    const int tig  = lane & 3;         // threadID_in_group
    const int n4   = tid & 31;         // float4 column for staging
    const int mr   = tid >> 5;         // staging row 0..7 (and +8)

    const float* Ag = cheb + (size_t)k * NN * NN + (size_t)mr * NN + n0 + n4 * 4;
    const float* Bg = xg + ((size_t)b * NN + mr) * 256 + coff + n4 * 4;

    float acc[4][4][4];
#pragma unroll
    for (int i = 0; i < 4; i++)
#pragma unroll
        for (int j = 0; j < 4; j++)
#pragma unroll
            for (int q = 0; q < 4; q++) acc[i][j][q] = 0.f;

    float4 pa0, pa1, pb0, pb1;
    // prefetch tile 0
    pa0 = *(const float4*)(Ag);
    pa1 = *(const float4*)(Ag + (size_t)8 * NN);
    pb0 = *(const float4*)(Bg);
    pb1 = *(const float4*)(Bg + 8 * 256);

    // stage tile 0 (rounded to tf32)
    *(float4*)&As[0][mr][n4 * 4]     = tf4(pa0);
    *(float4*)&As[0][mr + 8][n4 * 4] = tf4(pa1);
    *(float4*)&Bs[0][mr][n4 * 4]     = tf4(pb0);
    *(float4*)&Bs[0][mr + 8][n4 * 4] = tf4(pb1);
    __syncthreads();

    const int NIT = NN / 16;   // 128
    for (int it = 0; it < NIT; ++it) {
        const int buf = it & 1;
        if (it + 1 < NIT) {
            const size_t moff = (size_t)(it + 1) * 16;
            pa0 = *(const float4*)(Ag + moff * NN);
            pa1 = *(const float4*)(Ag + (moff + 8) * NN);
            pb0 = *(const float4*)(Bg + moff * 256);
            pb1 = *(const float4*)(Bg + (moff + 8) * 256);
        }
#pragma unroll
        for (int kk = 0; kk < 2; ++kk) {
            const int c0 = kk * 8 + tig;
            const int c1 = c0 + 4;
            float a[4][4];
            float bf[4][2];
#pragma unroll
            for (int fm = 0; fm < 4; ++fm) {
                const int r0 = wm + fm * 16 + gid;
                a[fm][0] = As[buf][c0][r0];
                a[fm][1] = As[buf][c0][r0 + 8];
                a[fm][2] = As[buf][c1][r0];
                a[fm][3] = As[buf][c1][r0 + 8];
            }
#pragma unroll
            for (int fn = 0; fn < 4; ++fn) {
                const int cc = wn + fn * 8 + gid;
                bf[fn][0] = Bs[buf][c0][cc];
                bf[fn][1] = Bs[buf][c1][cc];
            }
#pragma unroll
            for (int fm = 0; fm < 4; ++fm)
#pragma unroll
                for (int fn = 0; fn < 4; ++fn) mma4(acc[fm][fn], a[fm], bf[fn]);
        }
        if (it + 1 < NIT) {
            const int nb = buf ^ 1;
            *(float4*)&As[nb][mr][n4 * 4]     = tf4(pa0);
            *(float4*)&As[nb][mr + 8][n4 * 4] = tf4(pa1);
            *(float4*)&Bs[nb][mr][n4 * 4]     = tf4(pb0);
            *(float4*)&Bs[nb][mr + 8][n4 * 4] = tf4(pb1);
            __syncthreads();
        }
    }

    float* Cg = g_rhs + (size_t)k * NN * COLS;
#pragma unroll
    for (int fm = 0; fm < 4; ++fm) {
        const int r = n0 + wm + fm * 16 + gid;
#pragma unroll
        for (int fn = 0; fn < 4; ++fn) {
            const int cc = col0 + wn + fn * 8 + tig * 2;
            *(float2*)(Cg + (size_t)r * COLS + cc)       = make_float2(acc[fm][fn][0], acc[fm][fn][1]);
            *(float2*)(Cg + (size_t)(r + 8) * COLS + cc) = make_float2(acc[fm][fn][2], acc[fm][fn][3]);
        }
    }
}

// ---------------------------------------------------------------------------
// Kernel 2: fused Theta-contraction + ReLU + time conv(1x3,pad1) + residual
//           1x1 conv + ReLU + LayerNorm(C) + output transpose.
// Block: 256 threads = 64 c-lanes x 4 n-lanes; 16 n per block (4 passes).
// R3/R4: conv weights read from transposed g_twT (coalesced, 1 wf/LDG).
// ---------------------------------------------------------------------------
__global__ __launch_bounds__(256) void epi_k(const float* __restrict__ xg,
                                             const float* __restrict__ Theta,
                                             const float* __restrict__ tb,
                                             const float* __restrict__ rsw,
                                             const float* __restrict__ rsb,
                                             const float* __restrict__ lg,
                                             const float* __restrict__ lb,
                                             float* __restrict__ out) {
    __shared__ float Th[3072];        // Theta [k*16+f][o], o contiguous (12 KB)
    __shared__ float U[4096];         // union: R[4][768] + X[4][256]  /  H[4][16][64]
    __shared__ float S[4][64][20];    // spatial[nl][ci][t] (20 KB); aliased as LN stage

    float* Sln = &S[0][0][0];         // LN stage: [qnl][c*17 + t], 4*1088 floats

    const int tid   = threadIdx.x;
    const int c     = tid & 63;
    const int nl    = tid >> 6;
    const int b     = blockIdx.x >> 7;          // 128 blocks per batch element
    const int nbase = (blockIdx.x & 127) * 16;
    const int lane  = tid & 31;

#pragma unroll
    for (int j = 0; j < 12; j++) Th[tid + j * 256] = Theta[tid + j * 256];

    float rw[16];
#pragma unroll
    for (int f = 0; f < 16; f++) rw[f] = rsw[c * 16 + f];
    const float bias0 = tb[c] + rsb[c];

    const float g1 = lg[lane], g2 = lg[lane + 32];
    const float be1 = lb[lane], be2 = lb[lane + 32];

    for (int p = 0; p < 4; ++p) {
        // ---- cooperative load: rhs chunks (768 floats per n) and x (256 per n)
#pragma unroll
        for (int j = 0; j < 3; j++) {
            const int idx = tid + j * 256;        // float4 index 0..767
            const int nll = idx / 192;
            const int li  = idx % 192;
            const int kk  = li >> 6;
            const int r4  = li & 63;
            const int nn  = nbase + p * 4 + nll;
            const float4 v = *(const float4*)(g_rhs + ((size_t)kk * NN + nn) * COLS +
                                              (size_t)b * 256 + r4 * 4);
            *(float4*)(U + idx * 4) = v;
        }
        {
            const int nll = tid >> 6, r4 = tid & 63;
            const int nn  = nbase + p * 4 + nll;
            const float4 v = *(const float4*)(xg + ((size_t)b * NN + nn) * 256 + r4 * 4);
            *(float4*)(U + 3072 + tid * 4) = v;
        }
        __syncthreads();

        // ---- spatial[o=c][t] = relu( sum_kf Theta[kf][c] * R[kf][t] )
        float s[16];
#pragma unroll
        for (int t = 0; t < 16; t++) s[t] = 0.f;
        const float* Rr = U + nl * 768;
#pragma unroll 8
        for (int kf = 0; kf < 48; ++kf) {
            const float w  = Th[kf * 64 + c];
            const float4 q0 = *(const float4*)(Rr + kf * 16);
            const float4 q1 = *(const float4*)(Rr + kf * 16 + 4);
            const float4 q2 = *(const float4*)(Rr + kf * 16 + 8);
            const float4 q3 = *(const float4*)(Rr + kf * 16 + 12);
            s[0] += w * q0.x;  s[1] += w * q0.y;  s[2]  += w * q0.z;  s[3]  += w * q0.w;
            s[4] += w * q1.x;  s[5] += w * q1.y;  s[6]  += w * q1.z;  s[7]  += w * q1.w;
            s[8] += w * q2.x;  s[9] += w * q2.y;  s[10] += w * q2.z;  s[11] += w * q2.w;
            s[12] += w * q3.x; s[13] += w * q3.y; s[14] += w * q3.z;  s[15] += w * q3.w;
        }
#pragma unroll
        for (int q = 0; q < 4; q++) {
            *(float4*)(&S[nl][c][q * 4]) =
                make_float4(fmaxf(s[q * 4], 0.f), fmaxf(s[q * 4 + 1], 0.f),
                            fmaxf(s[q * 4 + 2], 0.f), fmaxf(s[q * 4 + 3], 0.f));
        }
        __syncthreads();

        // ---- h[t] = (time_b+res_b) + residual 1x1 + time conv (1x3, pad 1)
        float h[16];
#pragma unroll
        for (int t = 0; t < 16; t++) h[t] = bias0;

        const float* Xr = U + 3072 + nl * 256;
#pragma unroll
        for (int f = 0; f < 16; f++) {
            const float w  = rw[f];
            const float4 q0 = *(const float4*)(Xr + f * 16);
            const float4 q1 = *(const float4*)(Xr + f * 16 + 4);
            const float4 q2 = *(const float4*)(Xr + f * 16 + 8);
            const float4 q3 = *(const float4*)(Xr + f * 16 + 12);
            h[0] += w * q0.x;  h[1] += w * q0.y;  h[2]  += w * q0.z;  h[3]  += w * q0.w;
            h[4] += w * q1.x;  h[5] += w * q1.y;  h[6]  += w * q1.z;  h[7]  += w * q1.w;
            h[8] += w * q2.x;  h[9] += w * q2.y;  h[10] += w * q2.z;  h[11] += w * q2.w;
            h[12] += w * q3.x; h[13] += w * q3.y; h[14] += w * q3.z;  h[15] += w * q3.w;
        }

        // ---- time conv: weights from transposed g_twT (lane-coalesced LDG,
        //      L1-resident 48 KB), spatial values broadcast from smem.
#pragma unroll 4
        for (int ci = 0; ci < 64; ++ci) {
            const float w0 = __ldg(g_twT + (ci * 3 + 0) * 64 + c);
            const float w1 = __ldg(g_twT + (ci * 3 + 1) * 64 + c);
            const float w2 = __ldg(g_twT + (ci * 3 + 2) * 64 + c);
            const float* Sr = &S[nl][ci][0];
            const float4 a0 = *(const float4*)(Sr);
            const float4 a1 = *(const float4*)(Sr + 4);
            const float4 a2 = *(const float4*)(Sr + 8);
            const float4 a3 = *(const float4*)(Sr + 12);
            const float sv[16] = {a0.x, a0.y, a0.z, a0.w, a1.x, a1.y, a1.z, a1.w,
                                  a2.x, a2.y, a2.z, a2.w, a3.x, a3.y, a3.z, a3.w};
#pragma unroll
            for (int t = 0; t < 16; t++) {
                float a = w1 * sv[t];
                if (t > 0)  a += w0 * sv[t - 1];
                if (t < 15) a += w2 * sv[t + 1];
                h[t] += a;
            }
        }
        __syncthreads();   // everyone done reading U (X) and S

        // ---- stage h = relu(.) into H[nl][t][c] (aliases R/X region)
#pragma unroll
        for (int t = 0; t < 16; t++) U[nl * 1024 + t * 64 + c] = fmaxf(h[t], 0.f);
        __syncthreads();

        // ---- LayerNorm over c (64) per (nl, t); write normalized to Sln stage
#pragma unroll
        for (int i = 0; i < 8; i++) {
            const int q   = (tid >> 5) * 8 + i;
            const int qnl = q >> 4, qt = q & 15;
            const float v1 = U[qnl * 1024 + qt * 64 + lane];
            const float v2 = U[qnl * 1024 + qt * 64 + lane + 32];
            float sm = v1 + v2, sq = v1 * v1 + v2 * v2;
#pragma unroll
            for (int o = 16; o > 0; o >>= 1) {
                sm += __shfl_xor_sync(0xffffffffu, sm, o);
                sq += __shfl_xor_sync(0xffffffffu, sq, o);
            }
            const float mu  = sm * 0.015625f;
            const float var = sq * 0.015625f - mu * mu;
            const float rs  = rsqrtf(var + 1e-5f);
            // Sln layout: [qnl][c*17 + t] (pad 17 -> conflict-free)
            Sln[qnl * 1088 + lane * 17 + qt]        = (v1 - mu) * rs * g1 + be1;
            Sln[qnl * 1088 + (lane + 32) * 17 + qt] = (v2 - mu) * rs * g2 + be2;
        }
        __syncthreads();

        // ---- coalesced copy-out: 4096 contiguous floats (out[b][nn][c][t])
        {
            float* ob = out + (((size_t)b * NN + nbase + p * 4) << 10);
#pragma unroll
            for (int j = 0; j < 16; j++) {
                const int idx = tid + j * 256;      // 0..4095
                const int qnl = idx >> 10;
                const int rem = idx & 1023;         // c*16 + t
                const int cc  = rem >> 4;
                const int tt  = rem & 15;
                ob[idx] = Sln[qnl * 1088 + cc * 17 + tt];
            }
        }
        __syncthreads();   // before next pass overwrites U / S
    }
}

// ---------------------------------------------------------------------------
extern "C" void kernel_launch(void* const* d_in, const int* in_sizes, int n_in,
                              void* d_out, int out_size) {
    const float* x      = (const float*)d_in[0];
    const float* cheb   = (const float*)d_in[1];
    const float* Theta  = (const float*)d_in[2];
    const float* time_w = (const float*)d_in[3];
    const float* time_b = (const float*)d_in[4];
    const float* res_w  = (const float*)d_in[5];
    const float* res_b  = (const float*)d_in[6];
    const float* ln_g   = (const float*)d_in[7];
    const float* ln_b   = (const float*)d_in[8];
    float* out = (float*)d_out;

    tr_k<<<48, 256>>>(time_w);                    // 12288 weights
    dim3 g1(COLS / 128, NN / 128, 3);             // 64 x 16 x 3
    gemm_k<<<g1, 256>>>(cheb, x);
    epi_k<<<4096, 256>>>(x, Theta, time_b, res_w, res_b, ln_g, ln_b, out);
}

// round 7
// speedup vs baseline: 2.2798x; 1.1796x over previous
#include <cuda_runtime.h>
#include <cstdint>
#include <cstddef>

#define NN   2048
#define BB   32
#define COLS 8192   // B * F_IN * T

// scratch
__device__ float g_rhs[50331648];    // rhs[k][n][b*256+f*16+t]  (201 MB)
__device__ float g_twT[12288];       // transposed time-conv weights
__device__ float g_chebR[12582912];  // tf32-rounded cheb  (50 MB)
__device__ float g_xR[16777216];     // tf32-rounded x     (67 MB)

// ---------------------------------------------------------------------------
__device__ __forceinline__ float to_tf32(float x) {
    uint32_t u;
    asm("cvt.rna.tf32.f32 %0, %1;" : "=r"(u) : "f"(x));
    return __uint_as_float(u);
}

__device__ __forceinline__ void mma4(float (&d)[4], const float (&a)[4], const float (&b)[2]) {
    const uint32_t* A = reinterpret_cast<const uint32_t*>(a);
    const uint32_t* B = reinterpret_cast<const uint32_t*>(b);
    asm volatile(
        "mma.sync.aligned.m16n8k8.row.col.f32.tf32.tf32.f32 "
        "{%0,%1,%2,%3},{%4,%5,%6,%7},{%8,%9},{%0,%1,%2,%3};\n"
        : "+f"(d[0]), "+f"(d[1]), "+f"(d[2]), "+f"(d[3])
        : "r"(A[0]), "r"(A[1]), "r"(A[2]), "r"(A[3]), "r"(B[0]), "r"(B[1]));
}

__device__ __forceinline__ void cpasync16(uint32_t dst, const void* src) {
    asm volatile("cp.async.cg.shared.global [%0], [%1], 16;\n" :: "r"(dst), "l"(src));
}

// ---------------------------------------------------------------------------
// prep kernels
// ---------------------------------------------------------------------------
__global__ __launch_bounds__(256) void tr_k(const float* __restrict__ tw) {
    const int i = blockIdx.x * 256 + threadIdx.x;   // i = c*192 + (ci*3+dt)
    const int c = i / 192;
    const int r = i % 192;
    g_twT[r * 64 + c] = tw[i];
}

__global__ __launch_bounds__(256) void rnd_cheb_k(const float* __restrict__ s) {
    const int i = blockIdx.x * 256 + threadIdx.x;
    const float4 v = *((const float4*)s + i);
    *((float4*)g_chebR + i) = make_float4(to_tf32(v.x), to_tf32(v.y), to_tf32(v.z), to_tf32(v.w));
}
__global__ __launch_bounds__(256) void rnd_x_k(const float* __restrict__ s) {
    const int i = blockIdx.x * 256 + threadIdx.x;
    const float4 v = *((const float4*)s + i);
    *((float4*)g_xR + i) = make_float4(to_tf32(v.x), to_tf32(v.y), to_tf32(v.z), to_tf32(v.w));
}

// ---------------------------------------------------------------------------
// GEMM v2: rhs[k][n][col] = sum_m chebR[k][m][n] * xR[b][m][ft]
// CTA tile 128(n) x 128(col), BK=16, 128 threads = 4 warps (2x2), warp 64x64.
// cp.async.cg 2-stage pipeline from pre-rounded inputs (33.8 KB smem, legal).
// ---------------------------------------------------------------------------
#define PADW 132
#define STG_F (16 * PADW)          // floats per operand per stage (2112)
#define SLOT_F (2 * STG_F)         // A + B per stage (4224)

__global__ __launch_bounds__(128) void gemm_k2() {
    __shared__ float sm[2 * SLOT_F];   // 33792 B

    const int k    = blockIdx.z;
    const int n0   = blockIdx.y * 128;
    const int col0 = blockIdx.x * 128;
    const int b    = col0 >> 8;
    const int coff = col0 & 255;

    const int tid  = threadIdx.x;
    const int lane = tid & 31;
    const int warp = tid >> 5;
    const int wm   = (warp & 1) * 64;
    const int wn   = (warp >> 1) * 64;
    const int gid  = lane >> 2;
    const int tig  = lane & 3;

    const uint32_t smb = (uint32_t)__cvta_generic_to_shared(sm);
    const float* Abase = g_chebR + (size_t)k * NN * NN;          // [m][n]
    const float* Bbase = g_xR + (size_t)b * NN * 256 + coff;     // [m][ft]

    float acc[4][8][4];
#pragma unroll
    for (int i = 0; i < 4; i++)
#pragma unroll
        for (int j = 0; j < 8; j++)
#pragma unroll
            for (int q = 0; q < 4; q++) acc[i][j][q] = 0.f;

    // issue one stage (16 k-rows) into slot sl for k-iter kt
    auto issue = [&](int sl, int kt) {
        const int m0 = kt * 16;
        const uint32_t base = smb + (uint32_t)(sl * SLOT_F) * 4;
#pragma unroll
        for (int j = 0; j < 4; j++) {
            const int id  = tid + j * 128;
            const int row = id >> 5;
            const int c16 = id & 31;
            cpasync16(base + (uint32_t)(row * PADW + c16 * 4) * 4,
                      Abase + (size_t)(m0 + row) * NN + n0 + c16 * 4);
            cpasync16(base + (uint32_t)(STG_F + row * PADW + c16 * 4) * 4,
                      Bbase + (size_t)(m0 + row) * 256 + c16 * 4);
        }
    };

    issue(0, 0);
    asm volatile("cp.async.commit_group;\n");

    const int NIT = NN / 16;   // 128
    for (int it = 0; it < NIT; ++it) {
        if (it + 1 < NIT) {
            issue((it + 1) & 1, it + 1);
            asm volatile("cp.async.commit_group;\n");
            asm volatile("cp.async.wait_group 1;\n");   // slot `it` complete
        } else {
            asm volatile("cp.async.wait_group 0;\n");
        }
        __syncthreads();

        const float* As = sm + (it & 1) * SLOT_F;          // [16][PADW] over n
        const float* Bs = As + STG_F;                      // [16][PADW] over col
#pragma unroll
        for (int kk = 0; kk < 2; ++kk) {
            const int c0 = kk * 8 + tig;
            const int c1 = c0 + 4;
            float a[4][4];
            float bf[8][2];
#pragma unroll
            for (int fm = 0; fm < 4; ++fm) {
                const int r0 = wm + fm * 16 + gid;
                a[fm][0] = As[c0 * PADW + r0];
                a[fm][1] = As[c0 * PADW + r0 + 8];
                a[fm][2] = As[c1 * PADW + r0];
                a[fm][3] = As[c1 * PADW + r0 + 8];
            }
#pragma unroll
            for (int fn = 0; fn < 8; ++fn) {
                const int cc = wn + fn * 8 + gid;
                bf[fn][0] = Bs[c0 * PADW + cc];
                bf[fn][1] = Bs[c1 * PADW + cc];
            }
#pragma unroll
            for (int fm = 0; fm < 4; ++fm)
#pragma unroll
                for (int fn = 0; fn < 8; ++fn) mma4(acc[fm][fn], a[fm], bf[fn]);
        }
        __syncthreads();   // protect slot (it&1) before it is re-issued
    }

    float* Cg = g_rhs + (size_t)k * NN * COLS;
#pragma unroll
    for (int fm = 0; fm < 4; ++fm) {
        const int r = n0 + wm + fm * 16 + gid;
#pragma unroll
        for (int fn = 0; fn < 8; ++fn) {
            const int cc = col0 + wn + fn * 8 + tig * 2;
            *(float2*)(Cg + (size_t)r * COLS + cc)       = make_float2(acc[fm][fn][0], acc[fm][fn][1]);
            *(float2*)(Cg + (size_t)(r + 8) * COLS + cc) = make_float2(acc[fm][fn][2], acc[fm][fn][3]);
        }
    }
}

// ---------------------------------------------------------------------------
// Kernel 2: fused epilogue (unchanged from R4 — validated at 2791us total)
// ---------------------------------------------------------------------------
__global__ __launch_bounds__(256) void epi_k(const float* __restrict__ xg,
                                             const float* __restrict__ Theta,
                                             const float* __restrict__ tb,
                                             const float* __restrict__ rsw,
                                             const float* __restrict__ rsb,
                                             const float* __restrict__ lg,
                                             const float* __restrict__ lb,
                                             float* __restrict__ out) {
    __shared__ float Th[3072];
    __shared__ float U[4096];
    __shared__ float S[4][64][20];

    float* Sln = &S[0][0][0];

    const int tid   = threadIdx.x;
    const int c     = tid & 63;
    const int nl    = tid >> 6;
    const int b     = blockIdx.x >> 7;
    const int nbase = (blockIdx.x & 127) * 16;
    const int lane  = tid & 31;

#pragma unroll
    for (int j = 0; j < 12; j++) Th[tid + j * 256] = Theta[tid + j * 256];

    float rw[16];
#pragma unroll
    for (int f = 0; f < 16; f++) rw[f] = rsw[c * 16 + f];
    const float bias0 = tb[c] + rsb[c];

    const float g1 = lg[lane], g2 = lg[lane + 32];
    const float be1 = lb[lane], be2 = lb[lane + 32];

    for (int p = 0; p < 4; ++p) {
#pragma unroll
        for (int j = 0; j < 3; j++) {
            const int idx = tid + j * 256;
            const int nll = idx / 192;
            const int li  = idx % 192;
            const int kk  = li >> 6;
            const int r4  = li & 63;
            const int nn  = nbase + p * 4 + nll;
            const float4 v = *(const float4*)(g_rhs + ((size_t)kk * NN + nn) * COLS +
                                              (size_t)b * 256 + r4 * 4);
            *(float4*)(U + idx * 4) = v;
        }
        {
            const int nll = tid >> 6, r4 = tid & 63;
            const int nn  = nbase + p * 4 + nll;
            const float4 v = *(const float4*)(xg + ((size_t)b * NN + nn) * 256 + r4 * 4);
            *(float4*)(U + 3072 + tid * 4) = v;
        }
        __syncthreads();

        float s[16];
#pragma unroll
        for (int t = 0; t < 16; t++) s[t] = 0.f;
        const float* Rr = U + nl * 768;
#pragma unroll 8
        for (int kf = 0; kf < 48; ++kf) {
            const float w  = Th[kf * 64 + c];
            const float4 q0 = *(const float4*)(Rr + kf * 16);
            const float4 q1 = *(const float4*)(Rr + kf * 16 + 4);
            const float4 q2 = *(const float4*)(Rr + kf * 16 + 8);
            const float4 q3 = *(const float4*)(Rr + kf * 16 + 12);
            s[0] += w * q0.x;  s[1] += w * q0.y;  s[2]  += w * q0.z;  s[3]  += w * q0.w;
            s[4] += w * q1.x;  s[5] += w * q1.y;  s[6]  += w * q1.z;  s[7]  += w * q1.w;
            s[8] += w * q2.x;  s[9] += w * q2.y;  s[10] += w * q2.z;  s[11] += w * q2.w;
            s[12] += w * q3.x; s[13] += w * q3.y; s[14] += w * q3.z;  s[15] += w * q3.w;
        }
#pragma unroll
        for (int q = 0; q < 4; q++) {
            *(float4*)(&S[nl][c][q * 4]) =
                make_float4(fmaxf(s[q * 4], 0.f), fmaxf(s[q * 4 + 1], 0.f),
                            fmaxf(s[q * 4 + 2], 0.f), fmaxf(s[q * 4 + 3], 0.f));
        }
        __syncthreads();

        float h[16];
#pragma unroll
        for (int t = 0; t < 16; t++) h[t] = bias0;

        const float* Xr = U + 3072 + nl * 256;
#pragma unroll
        for (int f = 0; f < 16; f++) {
            const float w  = rw[f];
            const float4 q0 = *(const float4*)(Xr + f * 16);
            const float4 q1 = *(const float4*)(Xr + f * 16 + 4);
            const float4 q2 = *(const float4*)(Xr + f * 16 + 8);
            const float4 q3 = *(const float4*)(Xr + f * 16 + 12);
            h[0] += w * q0.x;  h[1] += w * q0.y;  h[2]  += w * q0.z;  h[3]  += w * q0.w;
            h[4] += w * q1.x;  h[5] += w * q1.y;  h[6]  += w * q1.z;  h[7]  += w * q1.w;
            h[8] += w * q2.x;  h[9] += w * q2.y;  h[10] += w * q2.z;  h[11] += w * q2.w;
            h[12] += w * q3.x; h[13] += w * q3.y; h[14] += w * q3.z;  h[15] += w * q3.w;
        }

#pragma unroll 4
        for (int ci = 0; ci < 64; ++ci) {
            const float w0 = __ldg(g_twT + (ci * 3 + 0) * 64 + c);
            const float w1 = __ldg(g_twT + (ci * 3 + 1) * 64 + c);
            const float w2 = __ldg(g_twT + (ci * 3 + 2) * 64 + c);
            const float* Sr = &S[nl][ci][0];
            const float4 a0 = *(const float4*)(Sr);
            const float4 a1 = *(const float4*)(Sr + 4);
            const float4 a2 = *(const float4*)(Sr + 8);
            const float4 a3 = *(const float4*)(Sr + 12);
            const float sv[16] = {a0.x, a0.y, a0.z, a0.w, a1.x, a1.y, a1.z, a1.w,
                                  a2.x, a2.y, a2.z, a2.w, a3.x, a3.y, a3.z, a3.w};
#pragma unroll
            for (int t = 0; t < 16; t++) {
                float a = w1 * sv[t];
                if (t > 0)  a += w0 * sv[t - 1];
                if (t < 15) a += w2 * sv[t + 1];
                h[t] += a;
            }
        }
        __syncthreads();

#pragma unroll
        for (int t = 0; t < 16; t++) U[nl * 1024 + t * 64 + c] = fmaxf(h[t], 0.f);
        __syncthreads();

#pragma unroll
        for (int i = 0; i < 8; i++) {
            const int q   = (tid >> 5) * 8 + i;
            const int qnl = q >> 4, qt = q & 15;
            const float v1 = U[qnl * 1024 + qt * 64 + lane];
            const float v2 = U[qnl * 1024 + qt * 64 + lane + 32];
            float sm = v1 + v2, sq = v1 * v1 + v2 * v2;
#pragma unroll
            for (int o = 16; o > 0; o >>= 1) {
                sm += __shfl_xor_sync(0xffffffffu, sm, o);
                sq += __shfl_xor_sync(0xffffffffu, sq, o);
            }
            const float mu  = sm * 0.015625f;
            const float var = sq * 0.015625f - mu * mu;
            const float rs  = rsqrtf(var + 1e-5f);
            Sln[qnl * 1088 + lane * 17 + qt]        = (v1 - mu) * rs * g1 + be1;
            Sln[qnl * 1088 + (lane + 32) * 17 + qt] = (v2 - mu) * rs * g2 + be2;
        }
        __syncthreads();

        {
            float* ob = out + (((size_t)b * NN + nbase + p * 4) << 10);
#pragma unroll
            for (int j = 0; j < 16; j++) {
                const int idx = tid + j * 256;
                const int qnl = idx >> 10;
                const int rem = idx & 1023;
                const int cc  = rem >> 4;
                const int tt  = rem & 15;
                ob[idx] = Sln[qnl * 1088 + cc * 17 + tt];
            }
        }
        __syncthreads();
    }
}

// ---------------------------------------------------------------------------
extern "C" void kernel_launch(void* const* d_in, const int* in_sizes, int n_in,
                              void* d_out, int out_size) {
    const float* x      = (const float*)d_in[0];
    const float* cheb   = (const float*)d_in[1];
    const float* Theta  = (const float*)d_in[2];
    const float* time_w = (const float*)d_in[3];
    const float* time_b = (const float*)d_in[4];
    const float* res_w  = (const float*)d_in[5];
    const float* res_b  = (const float*)d_in[6];
    const float* ln_g   = (const float*)d_in[7];
    const float* ln_b   = (const float*)d_in[8];
    float* out = (float*)d_out;

    tr_k<<<48, 256>>>(time_w);
    rnd_cheb_k<<<12288, 256>>>(cheb);   // 3*2048*2048 / 4 / 256
    rnd_x_k<<<16384, 256>>>(x);         // 32*2048*256 / 4 / 256

    dim3 g1(COLS / 128, NN / 128, 3);   // 64 x 16 x 3
    gemm_k2<<<g1, 128>>>();
    epi_k<<<4096, 256>>>(x, Theta, time_b, res_w, res_b, ln_g, ln_b, out);
}

// round 8
// speedup vs baseline: 2.4286x; 1.0653x over previous
#include <cuda_runtime.h>
#include <cstdint>
#include <cstddef>

#define NN   2048
#define BB   32
#define COLS 8192   // B * F_IN * T

// scratch
__device__ float g_rhs[50331648];    // rhs[k][n][b*256+f*16+t]  (201 MB)
__device__ float g_twT[12288];       // transposed time-conv weights
__device__ float g_chebR[12582912];  // tf32-rounded cheb  (50 MB)
__device__ float g_xR[16777216];     // tf32-rounded x     (67 MB)

// ---------------------------------------------------------------------------
__device__ __forceinline__ float to_tf32(float x) {
    uint32_t u;
    asm("cvt.rna.tf32.f32 %0, %1;" : "=r"(u) : "f"(x));
    return __uint_as_float(u);
}

__device__ __forceinline__ void mma4(float (&d)[4], const float (&a)[4], const float (&b)[2]) {
    const uint32_t* A = reinterpret_cast<const uint32_t*>(a);
    const uint32_t* B = reinterpret_cast<const uint32_t*>(b);
    asm volatile(
        "mma.sync.aligned.m16n8k8.row.col.f32.tf32.tf32.f32 "
        "{%0,%1,%2,%3},{%4,%5,%6,%7},{%8,%9},{%0,%1,%2,%3};\n"
        : "+f"(d[0]), "+f"(d[1]), "+f"(d[2]), "+f"(d[3])
        : "r"(A[0]), "r"(A[1]), "r"(A[2]), "r"(A[3]), "r"(B[0]), "r"(B[1]));
}

__device__ __forceinline__ void cpasync16(uint32_t dst, const void* src) {
    asm volatile("cp.async.cg.shared.global [%0], [%1], 16;\n" :: "r"(dst), "l"(src));
}

// ---------------------------------------------------------------------------
// prep kernels
// ---------------------------------------------------------------------------
__global__ __launch_bounds__(256) void tr_k(const float* __restrict__ tw) {
    const int i = blockIdx.x * 256 + threadIdx.x;   // i = c*192 + (ci*3+dt)
    const int c = i / 192;
    const int r = i % 192;
    g_twT[r * 64 + c] = tw[i];
}

__global__ __launch_bounds__(256) void rnd_cheb_k(const float* __restrict__ s) {
    const int i = blockIdx.x * 256 + threadIdx.x;
    const float4 v = *((const float4*)s + i);
    *((float4*)g_chebR + i) = make_float4(to_tf32(v.x), to_tf32(v.y), to_tf32(v.z), to_tf32(v.w));
}
__global__ __launch_bounds__(256) void rnd_x_k(const float* __restrict__ s) {
    const int i = blockIdx.x * 256 + threadIdx.x;
    const float4 v = *((const float4*)s + i);
    *((float4*)g_xR + i) = make_float4(to_tf32(v.x), to_tf32(v.y), to_tf32(v.z), to_tf32(v.w));
}

// ---------------------------------------------------------------------------
// GEMM v3: rhs[k][n][col] = sum_m chebR[k][m][n] * xR[b][m][ft]
// CTA tile 128(n) x 128(col), BK=16, 128 threads = 4 warps (2x2), warp 64x64.
// R7: PADW=136 (stride%32==8 -> conflict-free LDS), 3-stage cp.async ring
// with ONE __syncthreads per k-iter, dynamic smem (52.2 KB).
// ---------------------------------------------------------------------------
#define PADW 136
#define STG_F (16 * PADW)          // floats per operand per stage (2176)
#define SLOT_F (2 * STG_F)         // A + B per stage (4352)
#define GEMM_SMEM (3 * SLOT_F * 4) // 52224 bytes

__global__ __launch_bounds__(128) void gemm_k3() {
    extern __shared__ float sm[];

    const int k    = blockIdx.z;
    const int n0   = blockIdx.y * 128;
    const int col0 = blockIdx.x * 128;
    const int b    = col0 >> 8;
    const int coff = col0 & 255;

    const int tid  = threadIdx.x;
    const int lane = tid & 31;
    const int warp = tid >> 5;
    const int wm   = (warp & 1) * 64;
    const int wn   = (warp >> 1) * 64;
    const int gid  = lane >> 2;
    const int tig  = lane & 3;

    const uint32_t smb = (uint32_t)__cvta_generic_to_shared(sm);
    const float* Abase = g_chebR + (size_t)k * NN * NN;          // [m][n]
    const float* Bbase = g_xR + (size_t)b * NN * 256 + coff;     // [m][ft]

    float acc[4][8][4];
#pragma unroll
    for (int i = 0; i < 4; i++)
#pragma unroll
        for (int j = 0; j < 8; j++)
#pragma unroll
            for (int q = 0; q < 4; q++) acc[i][j][q] = 0.f;

    // issue one stage (16 k-rows) into slot sl for k-iter kt
    auto issue = [&](int sl, int kt) {
        const int m0 = kt * 16;
        const uint32_t base = smb + (uint32_t)(sl * SLOT_F) * 4;
#pragma unroll
        for (int j = 0; j < 4; j++) {
            const int id  = tid + j * 128;
            const int row = id >> 5;
            const int c16 = id & 31;
            cpasync16(base + (uint32_t)(row * PADW + c16 * 4) * 4,
                      Abase + (size_t)(m0 + row) * NN + n0 + c16 * 4);
            cpasync16(base + (uint32_t)(STG_F + row * PADW + c16 * 4) * 4,
                      Bbase + (size_t)(m0 + row) * 256 + c16 * 4);
        }
    };

    issue(0, 0);
    asm volatile("cp.async.commit_group;\n");
    issue(1, 1);
    asm volatile("cp.async.commit_group;\n");

    const int NIT = NN / 16;   // 128
    int sl = 0;                 // slot of iter `it`
    for (int it = 0; it < NIT; ++it) {
        asm volatile("cp.async.wait_group 1;\n");   // stage `it` resident
        __syncthreads();                            // all threads' copies visible
                                                    // + slot (it+2)%3 free (computed it-1)
        if (it + 2 < NIT) {
            issue(sl == 0 ? 2 : sl - 1, it + 2);    // (it+2)%3
            asm volatile("cp.async.commit_group;\n");
        }

        const float* As = sm + sl * SLOT_F;         // [16][PADW] over n
        const float* Bs = As + STG_F;               // [16][PADW] over col
#pragma unroll
        for (int kk = 0; kk < 2; ++kk) {
            const int c0 = kk * 8 + tig;
            const int c1 = c0 + 4;
            float a[4][4];
            float bf[8][2];
#pragma unroll
            for (int fm = 0; fm < 4; ++fm) {
                const int r0 = wm + fm * 16 + gid;
                a[fm][0] = As[c0 * PADW + r0];
                a[fm][1] = As[c0 * PADW + r0 + 8];
                a[fm][2] = As[c1 * PADW + r0];
                a[fm][3] = As[c1 * PADW + r0 + 8];
            }
#pragma unroll
            for (int fn = 0; fn < 8; ++fn) {
                const int cc = wn + fn * 8 + gid;
                bf[fn][0] = Bs[c0 * PADW + cc];
                bf[fn][1] = Bs[c1 * PADW + cc];
            }
#pragma unroll
            for (int fm = 0; fm < 4; ++fm)
#pragma unroll
                for (int fn = 0; fn < 8; ++fn) mma4(acc[fm][fn], a[fm], bf[fn]);
        }
        sl = (sl == 2) ? 0 : sl + 1;
    }

    float* Cg = g_rhs + (size_t)k * NN * COLS;
#pragma unroll
    for (int fm = 0; fm < 4; ++fm) {
        const int r = n0 + wm + fm * 16 + gid;
#pragma unroll
        for (int fn = 0; fn < 8; ++fn) {
            const int cc = col0 + wn + fn * 8 + tig * 2;
            *(float2*)(Cg + (size_t)r * COLS + cc)       = make_float2(acc[fm][fn][0], acc[fm][fn][1]);
            *(float2*)(Cg + (size_t)(r + 8) * COLS + cc) = make_float2(acc[fm][fn][2], acc[fm][fn][3]);
        }
    }
}

// ---------------------------------------------------------------------------
// Kernel 2: fused epilogue (unchanged — validated)
// ---------------------------------------------------------------------------
__global__ __launch_bounds__(256) void epi_k(const float* __restrict__ xg,
                                             const float* __restrict__ Theta,
                                             const float* __restrict__ tb,
                                             const float* __restrict__ rsw,
                                             const float* __restrict__ rsb,
                                             const float* __restrict__ lg,
                                             const float* __restrict__ lb,
                                             float* __restrict__ out) {
    __shared__ float Th[3072];
    __shared__ float U[4096];
    __shared__ float S[4][64][20];

    float* Sln = &S[0][0][0];

    const int tid   = threadIdx.x;
    const int c     = tid & 63;
    const int nl    = tid >> 6;
    const int b     = blockIdx.x >> 7;
    const int nbase = (blockIdx.x & 127) * 16;
    const int lane  = tid & 31;

#pragma unroll
    for (int j = 0; j < 12; j++) Th[tid + j * 256] = Theta[tid + j * 256];

    float rw[16];
#pragma unroll
    for (int f = 0; f < 16; f++) rw[f] = rsw[c * 16 + f];
    const float bias0 = tb[c] + rsb[c];

    const float g1 = lg[lane], g2 = lg[lane + 32];
    const float be1 = lb[lane], be2 = lb[lane + 32];

    for (int p = 0; p < 4; ++p) {
#pragma unroll
        for (int j = 0; j < 3; j++) {
            const int idx = tid + j * 256;
            const int nll = idx / 192;
            const int li  = idx % 192;
            const int kk  = li >> 6;
            const int r4  = li & 63;
            const int nn  = nbase + p * 4 + nll;
            const float4 v = *(const float4*)(g_rhs + ((size_t)kk * NN + nn) * COLS +
                                              (size_t)b * 256 + r4 * 4);
            *(float4*)(U + idx * 4) = v;
        }
        {
            const int nll = tid >> 6, r4 = tid & 63;
            const int nn  = nbase + p * 4 + nll;
            const float4 v = *(const float4*)(xg + ((size_t)b * NN + nn) * 256 + r4 * 4);
            *(float4*)(U + 3072 + tid * 4) = v;
        }
        __syncthreads();

        float s[16];
#pragma unroll
        for (int t = 0; t < 16; t++) s[t] = 0.f;
        const float* Rr = U + nl * 768;
#pragma unroll 8
        for (int kf = 0; kf < 48; ++kf) {
            const float w  = Th[kf * 64 + c];
            const float4 q0 = *(const float4*)(Rr + kf * 16);
            const float4 q1 = *(const float4*)(Rr + kf * 16 + 4);
            const float4 q2 = *(const float4*)(Rr + kf * 16 + 8);
            const float4 q3 = *(const float4*)(Rr + kf * 16 + 12);
            s[0] += w * q0.x;  s[1] += w * q0.y;  s[2]  += w * q0.z;  s[3]  += w * q0.w;
            s[4] += w * q1.x;  s[5] += w * q1.y;  s[6]  += w * q1.z;  s[7]  += w * q1.w;
            s[8] += w * q2.x;  s[9] += w * q2.y;  s[10] += w * q2.z;  s[11] += w * q2.w;
            s[12] += w * q3.x; s[13] += w * q3.y; s[14] += w * q3.z;  s[15] += w * q3.w;
        }
#pragma unroll
        for (int q = 0; q < 4; q++) {
            *(float4*)(&S[nl][c][q * 4]) =
                make_float4(fmaxf(s[q * 4], 0.f), fmaxf(s[q * 4 + 1], 0.f),
                            fmaxf(s[q * 4 + 2], 0.f), fmaxf(s[q * 4 + 3], 0.f));
        }
        __syncthreads();

        float h[16];
#pragma unroll
        for (int t = 0; t < 16; t++) h[t] = bias0;

        const float* Xr = U + 3072 + nl * 256;
#pragma unroll
        for (int f = 0; f < 16; f++) {
            const float w  = rw[f];
            const float4 q0 = *(const float4*)(Xr + f * 16);
            const float4 q1 = *(const float4*)(Xr + f * 16 + 4);
            const float4 q2 = *(const float4*)(Xr + f * 16 + 8);
            const float4 q3 = *(const float4*)(Xr + f * 16 + 12);
            h[0] += w * q0.x;  h[1] += w * q0.y;  h[2]  += w * q0.z;  h[3]  += w * q0.w;
            h[4] += w * q1.x;  h[5] += w * q1.y;  h[6]  += w * q1.z;  h[7]  += w * q1.w;
            h[8] += w * q2.x;  h[9] += w * q2.y;  h[10] += w * q2.z;  h[11] += w * q2.w;
            h[12] += w * q3.x; h[13] += w * q3.y; h[14] += w * q3.z;  h[15] += w * q3.w;
        }

#pragma unroll 4
        for (int ci = 0; ci < 64; ++ci) {
            const float w0 = __ldg(g_twT + (ci * 3 + 0) * 64 + c);
            const float w1 = __ldg(g_twT + (ci * 3 + 1) * 64 + c);
            const float w2 = __ldg(g_twT + (ci * 3 + 2) * 64 + c);
            const float* Sr = &S[nl][ci][0];
            const float4 a0 = *(const float4*)(Sr);
            const float4 a1 = *(const float4*)(Sr + 4);
            const float4 a2 = *(const float4*)(Sr + 8);
            const float4 a3 = *(const float4*)(Sr + 12);
            const float sv[16] = {a0.x, a0.y, a0.z, a0.w, a1.x, a1.y, a1.z, a1.w,
                                  a2.x, a2.y, a2.z, a2.w, a3.x, a3.y, a3.z, a3.w};
#pragma unroll
            for (int t = 0; t < 16; t++) {
                float a = w1 * sv[t];
                if (t > 0)  a += w0 * sv[t - 1];
                if (t < 15) a += w2 * sv[t + 1];
                h[t] += a;
            }
        }
        __syncthreads();

#pragma unroll
        for (int t = 0; t < 16; t++) U[nl * 1024 + t * 64 + c] = fmaxf(h[t], 0.f);
        __syncthreads();

#pragma unroll
        for (int i = 0; i < 8; i++) {
            const int q   = (tid >> 5) * 8 + i;
            const int qnl = q >> 4, qt = q & 15;
            const float v1 = U[qnl * 1024 + qt * 64 + lane];
            const float v2 = U[qnl * 1024 + qt * 64 + lane + 32];
            float sm = v1 + v2, sq = v1 * v1 + v2 * v2;
#pragma unroll
            for (int o = 16; o > 0; o >>= 1) {
                sm += __shfl_xor_sync(0xffffffffu, sm, o);
                sq += __shfl_xor_sync(0xffffffffu, sq, o);
            }
            const float mu  = sm * 0.015625f;
            const float var = sq * 0.015625f - mu * mu;
            const float rs  = rsqrtf(var + 1e-5f);
            Sln[qnl * 1088 + lane * 17 + qt]        = (v1 - mu) * rs * g1 + be1;
            Sln[qnl * 1088 + (lane + 32) * 17 + qt] = (v2 - mu) * rs * g2 + be2;
        }
        __syncthreads();

        {
            float* ob = out + (((size_t)b * NN + nbase + p * 4) << 10);
#pragma unroll
            for (int j = 0; j < 16; j++) {
                const int idx = tid + j * 256;
                const int qnl = idx >> 10;
                const int rem = idx & 1023;
                const int cc  = rem >> 4;
                const int tt  = rem & 15;
                ob[idx] = Sln[qnl * 1088 + cc * 17 + tt];
            }
        }
        __syncthreads();
    }
}

// ---------------------------------------------------------------------------
extern "C" void kernel_launch(void* const* d_in, const int* in_sizes, int n_in,
                              void* d_out, int out_size) {
    const float* x      = (const float*)d_in[0];
    const float* cheb   = (const float*)d_in[1];
    const float* Theta  = (const float*)d_in[2];
    const float* time_w = (const float*)d_in[3];
    const float* time_b = (const float*)d_in[4];
    const float* res_w  = (const float*)d_in[5];
    const float* res_b  = (const float*)d_in[6];
    const float* ln_g   = (const float*)d_in[7];
    const float* ln_b   = (const float*)d_in[8];
    float* out = (float*)d_out;

    // idempotent, capture-safe (not a stream op, no allocation)
    cudaFuncSetAttribute(gemm_k3, cudaFuncAttributeMaxDynamicSharedMemorySize, GEMM_SMEM);

    tr_k<<<48, 256>>>(time_w);
    rnd_cheb_k<<<12288, 256>>>(cheb);   // 3*2048*2048 / 4 / 256
    rnd_x_k<<<16384, 256>>>(x);         // 32*2048*256 / 4 / 256

    dim3 g1(COLS / 128, NN / 128, 3);   // 64 x 16 x 3
    gemm_k3<<<g1, 128, GEMM_SMEM>>>();
    epi_k<<<4096, 256>>>(x, Theta, time_b, res_w, res_b, ln_g, ln_b, out);
}